// round 2
// baseline (speedup 1.0000x reference)
#include <cuda_runtime.h>
#include <cstdint>

#define NB 64
#define NC 2048
#define NPOS9 729          // 27*27
#define TOTPOS (NB*NPOS9)  // 46656
#define KSEL 819

__device__ float g_conv[(size_t)NB * NPOS9 * NC];  // NHWC: [b][p][c]
__device__ float g_t1[TOTPOS];
__device__ float g_t2[TOTPOS];

// ---------------------------------------------------------------------------
// Kernel 1: conv (VALID, stride 1) -> NHWC scratch.  fp32 via fma.rn.f32x2.
// grid (16 channel-tiles, 64 batches), 256 threads.
// Thread tile: 8 channels x 8 positions (accumulators as f32x2 pairs).
// ---------------------------------------------------------------------------
#define WS_STRIDE 130
#define CONV_SMEM ((3 * 1024 + 108 * WS_STRIDE) * 4)

__global__ void __launch_bounds__(256) conv_kernel(const float* __restrict__ x,
                                                   const float* __restrict__ w)
{
    extern __shared__ float smem[];
    float* xs = smem;            // 3*32*32
    float* ws = smem + 3 * 1024; // [k=108][ch=128] padded stride 130

    const int b = blockIdx.y;
    const int c0 = blockIdx.x * 128;
    const int tid = threadIdx.x;

    {
        const float4* xsrc = (const float4*)(x + (size_t)b * 3072);
        float4* xdst = (float4*)xs;
        #pragma unroll
        for (int i = 0; i < 3; i++) xdst[tid + 256 * i] = xsrc[tid + 256 * i];
    }
    for (int idx = tid; idx < 128 * 108; idx += 256) {
        int ch = idx / 108, k = idx - ch * 108;
        ws[k * WS_STRIDE + ch] = w[(size_t)(c0 + ch) * 108 + k];
    }
    __syncthreads();

    const int ch_tid = tid & 15;
    const int pos_tid = tid >> 4;
    const int ch0 = ch_tid * 8;

    for (int chunk = 0; chunk < 6; chunk++) {
        const int p0 = chunk * 128 + pos_tid * 8;
        int pbase[8];
        #pragma unroll
        for (int pp = 0; pp < 8; pp++) {
            int p = p0 + pp; if (p > 728) p = 728;
            int y = p / 27;
            pbase[pp] = y * 32 + (p - y * 27);
        }
        unsigned long long acc0[8], acc1[8], acc2[8], acc3[8];
        #pragma unroll
        for (int pp = 0; pp < 8; pp++) { acc0[pp] = 0ull; acc1[pp] = 0ull; acc2[pp] = 0ull; acc3[pp] = 0ull; }

        #pragma unroll 1
        for (int c = 0; c < 3; c++) {
            #pragma unroll 1
            for (int i = 0; i < 6; i++) {
                const float* xrow = xs + c * 1024 + i * 32;
                const float* wk = ws + (c * 36 + i * 6) * WS_STRIDE + ch0;
                #pragma unroll
                for (int j = 0; j < 6; j++) {
                    const unsigned long long* wp = (const unsigned long long*)(wk + j * WS_STRIDE);
                    unsigned long long w0 = wp[0], w1 = wp[1], w2 = wp[2], w3 = wp[3];
                    #pragma unroll
                    for (int pp = 0; pp < 8; pp++) {
                        float xv = xrow[pbase[pp] + j];
                        unsigned long long xx;
                        asm("mov.b64 %0, {%1, %1};" : "=l"(xx) : "f"(xv));
                        asm("fma.rn.f32x2 %0, %1, %2, %0;" : "+l"(acc0[pp]) : "l"(w0), "l"(xx));
                        asm("fma.rn.f32x2 %0, %1, %2, %0;" : "+l"(acc1[pp]) : "l"(w1), "l"(xx));
                        asm("fma.rn.f32x2 %0, %1, %2, %0;" : "+l"(acc2[pp]) : "l"(w2), "l"(xx));
                        asm("fma.rn.f32x2 %0, %1, %2, %0;" : "+l"(acc3[pp]) : "l"(w3), "l"(xx));
                    }
                }
            }
        }
        #pragma unroll
        for (int pp = 0; pp < 8; pp++) {
            int p = p0 + pp;
            if (p < 729) {
                float* dst = g_conv + ((size_t)(b * NPOS9 + p)) * NC + c0 + ch0;
                float a, bb, cc, dd, e, f, g, h;
                asm("mov.b64 {%0, %1}, %2;" : "=f"(a), "=f"(bb) : "l"(acc0[pp]));
                asm("mov.b64 {%0, %1}, %2;" : "=f"(cc), "=f"(dd) : "l"(acc1[pp]));
                asm("mov.b64 {%0, %1}, %2;" : "=f"(e), "=f"(f) : "l"(acc2[pp]));
                asm("mov.b64 {%0, %1}, %2;" : "=f"(g), "=f"(h) : "l"(acc3[pp]));
                ((float4*)dst)[0] = make_float4(a, bb, cc, dd);
                ((float4*)dst)[1] = make_float4(e, f, g, h);
            }
        }
    }
}

// ---------------------------------------------------------------------------
// Kernel 2: per-position 820th-smallest of (bias - v) and (bias + v)
// via MSB-first 8-bit radix select on order-preserving uint keys.
// One warp per position; both branches share one data sweep per pass.
// ---------------------------------------------------------------------------
__device__ __forceinline__ unsigned f2u(float f) {
    unsigned b = __float_as_uint(f);
    return (b & 0x80000000u) ? ~b : (b | 0x80000000u);
}
__device__ __forceinline__ float u2f(unsigned u) {
    unsigned b = (u & 0x80000000u) ? (u & 0x7fffffffu) : ~u;
    return __uint_as_float(b);
}

__device__ __forceinline__ void radix_step(const int* hist, unsigned& rank, unsigned& pfx, int lane)
{
    int loc[8]; int s = 0;
    #pragma unroll
    for (int d = 0; d < 8; d++) { loc[d] = hist[lane * 8 + d]; s += loc[d]; }
    int incl = s;
    #pragma unroll
    for (int o = 1; o < 32; o <<= 1) {
        int n = __shfl_up_sync(0xffffffffu, incl, o);
        if (lane >= o) incl += n;
    }
    int before = incl - s;
    int digit = -1; unsigned nr = 0;
    #pragma unroll
    for (int d = 0; d < 8; d++) {
        if (digit < 0 && (int)rank >= before && (int)rank < before + loc[d]) {
            digit = lane * 8 + d; nr = rank - (unsigned)before;
        }
        before += loc[d];
    }
    unsigned bal = __ballot_sync(0xffffffffu, digit >= 0);
    int src = __ffs(bal) - 1;
    digit = __shfl_sync(0xffffffffu, digit, src);
    nr = (unsigned)__shfl_sync(0xffffffffu, (int)nr, src);
    pfx = (pfx << 8) | (unsigned)digit;
    rank = nr;
}

#define SEL_SMEM ((2048 + 4 * 2048 + 4 * 512) * 4)

__global__ void __launch_bounds__(128) select_kernel(const float* __restrict__ bias)
{
    extern __shared__ float smem[];
    float* sbias = smem;                       // 2048
    float* sval  = smem + 2048;                // 4 warps * 2048
    int*   shist = (int*)(smem + 2048 + 4 * 2048); // 4 warps * 512

    const int tid = threadIdx.x;
    const int wid = tid >> 5, lane = tid & 31;

    {
        const float4* bsrc = (const float4*)bias;
        float4* bdst = (float4*)sbias;
        #pragma unroll
        for (int i = 0; i < 4; i++) bdst[tid + 128 * i] = bsrc[tid + 128 * i];
    }
    __syncthreads();

    const int pos = blockIdx.x * 4 + wid;
    float* sv = sval + wid * 2048;
    int* hw = shist + wid * 512;

    {
        const float4* src = (const float4*)(g_conv + (size_t)pos * NC);
        float4* dst = (float4*)sv;
        #pragma unroll
        for (int t = 0; t < 16; t++) dst[t * 32 + lane] = src[t * 32 + lane];
    }
    __syncwarp();

    unsigned rank1 = KSEL, rank2 = KSEL, pfx1 = 0, pfx2 = 0;
    for (int pass = 0; pass < 4; pass++) {
        const int shift = 24 - pass * 8;
        #pragma unroll
        for (int i = 0; i < 16; i++) hw[i * 32 + lane] = 0;
        __syncwarp();
        for (int t = 0; t < 64; t++) {
            int c = t * 32 + lane;
            float v = sv[c];
            float bb = sbias[c];
            unsigned u1 = f2u(bb - v);
            unsigned u2 = f2u(bb + v);
            unsigned hi1 = u1 >> shift;
            unsigned hi2 = u2 >> shift;
            bool a1 = (hi1 >> 8) == pfx1;
            bool a2 = (hi2 >> 8) == pfx2;
            unsigned d1 = hi1 & 255u, d2 = hi2 & 255u;
            unsigned k1 = a1 ? d1 : (0x1000u + lane);
            unsigned g1 = __match_any_sync(0xffffffffu, k1);
            if (a1 && lane == __ffs(g1) - 1) atomicAdd(&hw[d1], __popc(g1));
            unsigned k2 = a2 ? d2 : (0x1000u + lane);
            unsigned g2 = __match_any_sync(0xffffffffu, k2);
            if (a2 && lane == __ffs(g2) - 1) atomicAdd(&hw[256 + d2], __popc(g2));
        }
        __syncwarp();
        radix_step(hw, rank1, pfx1, lane);
        radix_step(hw + 256, rank2, pfx2, lane);
        __syncwarp();
    }
    if (lane == 0) {
        g_t1[pos] = u2f(pfx1);
        g_t2[pos] = u2f(pfx2);
    }
}

// ---------------------------------------------------------------------------
// Kernel 3: masks + (avg_pool_ceil(5,3) o adaptive(6)) as separable 6x27 map A.
// grid (16 channel-tiles, 64 batches), 128 threads = 1 channel/thread.
// ---------------------------------------------------------------------------
__global__ void __launch_bounds__(128) pool_kernel(const float* __restrict__ bias,
                                                   float* __restrict__ out)
{
    __shared__ float st1[NPOS9], st2[NPOS9];
    __shared__ float sA[6][28];

    const int b = blockIdx.y;
    const int c = blockIdx.x * 128 + threadIdx.x;

    for (int i = threadIdx.x; i < NPOS9; i += 128) {
        st1[i] = g_t1[b * NPOS9 + i];
        st2[i] = g_t2[b * NPOS9 + i];
    }
    if (threadIdx.x < 27) {
        int wcol = threadIdx.x;
        const int sidx[6] = {0, 1, 3, 4, 6, 7};
        #pragma unroll
        for (int i = 0; i < 6; i++) {
            float a = 0.0f;
            #pragma unroll
            for (int q = 0; q < 2; q++) {
                int p = sidx[i] + q;
                int st = 3 * p, en = (st + 5 < 27) ? st + 5 : 27;
                if (wcol >= st && wcol < en) a += 0.5f / (float)(en - st);
            }
            sA[i][wcol] = a;
        }
    }
    __syncthreads();

    const float bc = bias[c];
    const float* p = g_conv + (size_t)b * NPOS9 * NC + c;

    float acc1[36], acc2[36];
    #pragma unroll
    for (int k = 0; k < 36; k++) { acc1[k] = 0.0f; acc2[k] = 0.0f; }

    int idx = 0;
    for (int h = 0; h < 27; h++) {
        float r1[6], r2[6];
        #pragma unroll
        for (int j = 0; j < 6; j++) { r1[j] = 0.0f; r2[j] = 0.0f; }
        for (int wcol = 0; wcol < 27; wcol++, idx++) {
            float v = __ldg(p + (size_t)idx * NC);
            float m1 = (bc - v < st1[idx]) ? 1.0f : 0.0f;
            float m2 = (bc + v < st2[idx]) ? 1.0f : 0.0f;
            #pragma unroll
            for (int j = 0; j < 6; j++) {
                float a = sA[j][wcol];
                r1[j] += a * m1;
                r2[j] += a * m2;
            }
        }
        #pragma unroll
        for (int i = 0; i < 6; i++) {
            float ah = sA[i][h];
            #pragma unroll
            for (int j = 0; j < 6; j++) {
                acc1[i * 6 + j] += ah * r1[j];
                acc2[i * 6 + j] += ah * r2[j];
            }
        }
    }

    float* o1 = out + ((size_t)(b * NC + c)) * 36;
    float* o2 = o1 + (size_t)NB * NC * 36;
    #pragma unroll
    for (int k = 0; k < 36; k++) { o1[k] = acc1[k]; o2[k] = acc2[k]; }
}

// ---------------------------------------------------------------------------
extern "C" void kernel_launch(void* const* d_in, const int* in_sizes, int n_in,
                              void* d_out, int out_size)
{
    const float* x    = (const float*)d_in[0]; // [64,3,32,32]
    const float* w    = (const float*)d_in[1]; // [2048,3,6,6]
    const float* bias = (const float*)d_in[2]; // [2048]
    float* out = (float*)d_out;                // [2][64,2048,6,6]

    cudaFuncSetAttribute(conv_kernel, cudaFuncAttributeMaxDynamicSharedMemorySize, CONV_SMEM);
    cudaFuncSetAttribute(select_kernel, cudaFuncAttributeMaxDynamicSharedMemorySize, SEL_SMEM);

    conv_kernel<<<dim3(16, 64), 256, CONV_SMEM>>>(x, w);
    select_kernel<<<TOTPOS / 4, 128, SEL_SMEM>>>(bias);
    pool_kernel<<<dim3(16, 64), 128>>>(bias, out);
}

// round 4
// speedup vs baseline: 3.5833x; 3.5833x over previous
#include <cuda_runtime.h>
#include <cstdint>

#define NB 64
#define NC 2048
#define NPOS9 729          // 27*27
#define TOTPOS (NB*NPOS9)  // 46656
#define KSEL 819
#define SEL_CAP 1024

__device__ float g_conv[(size_t)NB * NPOS9 * NC];  // NHWC: [b][p][c]
__device__ float g_t1[TOTPOS];
__device__ float g_t2[TOTPOS];

// ---------------------------------------------------------------------------
// Kernel 1: conv (VALID, stride 1) -> NHWC scratch.  fp32 via fma.rn.f32x2.
// ---------------------------------------------------------------------------
#define WS_STRIDE 130
#define CONV_SMEM ((3 * 1024 + 108 * WS_STRIDE) * 4)

__global__ void __launch_bounds__(256) conv_kernel(const float* __restrict__ x,
                                                   const float* __restrict__ w)
{
    extern __shared__ float smem[];
    float* xs = smem;            // 3*32*32
    float* ws = smem + 3 * 1024; // [k=108][ch=128] padded stride 130

    const int b = blockIdx.y;
    const int c0 = blockIdx.x * 128;
    const int tid = threadIdx.x;

    {
        const float4* xsrc = (const float4*)(x + (size_t)b * 3072);
        float4* xdst = (float4*)xs;
        #pragma unroll
        for (int i = 0; i < 3; i++) xdst[tid + 256 * i] = xsrc[tid + 256 * i];
    }
    for (int idx = tid; idx < 128 * 108; idx += 256) {
        int ch = idx / 108, k = idx - ch * 108;
        ws[k * WS_STRIDE + ch] = w[(size_t)(c0 + ch) * 108 + k];
    }
    __syncthreads();

    const int ch_tid = tid & 15;
    const int pos_tid = tid >> 4;
    const int ch0 = ch_tid * 8;

    for (int chunk = 0; chunk < 6; chunk++) {
        const int p0 = chunk * 128 + pos_tid * 8;
        int pbase[8];
        #pragma unroll
        for (int pp = 0; pp < 8; pp++) {
            int p = p0 + pp; if (p > 728) p = 728;
            int y = p / 27;
            pbase[pp] = y * 32 + (p - y * 27);
        }
        unsigned long long acc0[8], acc1[8], acc2[8], acc3[8];
        #pragma unroll
        for (int pp = 0; pp < 8; pp++) { acc0[pp] = 0ull; acc1[pp] = 0ull; acc2[pp] = 0ull; acc3[pp] = 0ull; }

        #pragma unroll 1
        for (int c = 0; c < 3; c++) {
            #pragma unroll 1
            for (int i = 0; i < 6; i++) {
                const float* xrow = xs + c * 1024 + i * 32;
                const float* wk = ws + (c * 36 + i * 6) * WS_STRIDE + ch0;
                #pragma unroll
                for (int j = 0; j < 6; j++) {
                    const unsigned long long* wp = (const unsigned long long*)(wk + j * WS_STRIDE);
                    unsigned long long w0 = wp[0], w1 = wp[1], w2 = wp[2], w3 = wp[3];
                    #pragma unroll
                    for (int pp = 0; pp < 8; pp++) {
                        float xv = xrow[pbase[pp] + j];
                        unsigned long long xx;
                        asm("mov.b64 %0, {%1, %1};" : "=l"(xx) : "f"(xv));
                        asm("fma.rn.f32x2 %0, %1, %2, %0;" : "+l"(acc0[pp]) : "l"(w0), "l"(xx));
                        asm("fma.rn.f32x2 %0, %1, %2, %0;" : "+l"(acc1[pp]) : "l"(w1), "l"(xx));
                        asm("fma.rn.f32x2 %0, %1, %2, %0;" : "+l"(acc2[pp]) : "l"(w2), "l"(xx));
                        asm("fma.rn.f32x2 %0, %1, %2, %0;" : "+l"(acc3[pp]) : "l"(w3), "l"(xx));
                    }
                }
            }
        }
        #pragma unroll
        for (int pp = 0; pp < 8; pp++) {
            int p = p0 + pp;
            if (p < 729) {
                float* dst = g_conv + ((size_t)(b * NPOS9 + p)) * NC + c0 + ch0;
                float a, bb, cc, dd, e, f, g, h;
                asm("mov.b64 {%0, %1}, %2;" : "=f"(a), "=f"(bb) : "l"(acc0[pp]));
                asm("mov.b64 {%0, %1}, %2;" : "=f"(cc), "=f"(dd) : "l"(acc1[pp]));
                asm("mov.b64 {%0, %1}, %2;" : "=f"(e), "=f"(f) : "l"(acc2[pp]));
                asm("mov.b64 {%0, %1}, %2;" : "=f"(g), "=f"(h) : "l"(acc3[pp]));
                ((float4*)dst)[0] = make_float4(a, bb, cc, dd);
                ((float4*)dst)[1] = make_float4(e, f, g, h);
            }
        }
    }
}

// ---------------------------------------------------------------------------
// Kernel 2: atomic-free radix select via ballot-transpose histograms.
// One warp per position; both branches (bias-v, bias+v) fused per sweep.
// ---------------------------------------------------------------------------
__device__ __forceinline__ unsigned f2u(float f) {
    int b = __float_as_int(f);
    return (unsigned)(b ^ ((b >> 31) | 0x80000000));
}
__device__ __forceinline__ float u2f(unsigned u) {
    unsigned b = (u & 0x80000000u) ? (u & 0x7fffffffu) : ~u;
    return __uint_as_float(b);
}

// per-lane count of 4-bit digit histogram; lanes 0-15: branch1 bins 0-15,
// lanes 16-31: branch2 bins 0-15.
// Match test: element digit == bin  <=>  for every bit k,
// ballot_k bit == bin bit k.  Mismatch indicator = ballot_k XOR r_k with
// r_k = ~0 when bin bit k is SET, 0 when clear.
template<bool MASKED>
__device__ __forceinline__ int hist_sweep(const float4* __restrict__ vsrc,
                                          const float* __restrict__ sbias,
                                          unsigned top1, unsigned top2,
                                          unsigned maskTop, int shift, int lane)
{
    const unsigned bin = lane & 15;
    const unsigned r0 = (bin & 1) ? ~0u : 0u;
    const unsigned r1 = (bin & 2) ? ~0u : 0u;
    const unsigned r2 = (bin & 4) ? ~0u : 0u;
    const unsigned r3 = (bin & 8) ? ~0u : 0u;
    const bool br2 = (lane >= 16);
    int cnt = 0;
    const float4* bs4 = (const float4*)sbias;
    for (int t = 0; t < 16; t++) {
        float4 v4 = __ldg(vsrc + t * 32 + lane);
        float4 b4 = bs4[t * 32 + lane];
        #pragma unroll
        for (int e = 0; e < 4; e++) {
            float v = (&v4.x)[e], bb = (&b4.x)[e];
            unsigned u1 = f2u(bb - v), u2 = f2u(bb + v);
            bool a1 = MASKED ? (((u1 ^ top1) & maskTop) == 0) : true;
            bool a2 = MASKED ? (((u2 ^ top2) & maskTop) == 0) : true;
            unsigned d1 = u1 >> shift, d2 = u2 >> shift;
            unsigned B10 = __ballot_sync(~0u, a1 && (d1 & 1));
            unsigned B11 = __ballot_sync(~0u, a1 && (d1 & 2));
            unsigned B12 = __ballot_sync(~0u, a1 && (d1 & 4));
            unsigned B13 = __ballot_sync(~0u, a1 && (d1 & 8));
            unsigned A1  = MASKED ? __ballot_sync(~0u, a1) : ~0u;
            unsigned B20 = __ballot_sync(~0u, a2 && (d2 & 1));
            unsigned B21 = __ballot_sync(~0u, a2 && (d2 & 2));
            unsigned B22 = __ballot_sync(~0u, a2 && (d2 & 4));
            unsigned B23 = __ballot_sync(~0u, a2 && (d2 & 8));
            unsigned A2  = MASKED ? __ballot_sync(~0u, a2) : ~0u;
            unsigned Bb0 = br2 ? B20 : B10;
            unsigned Bb1 = br2 ? B21 : B11;
            unsigned Bb2 = br2 ? B22 : B12;
            unsigned Bb3 = br2 ? B23 : B13;
            unsigned A   = br2 ? A2  : A1;
            unsigned mm = A & ~((Bb3 ^ r3) | (Bb2 ^ r2) | (Bb1 ^ r1) | (Bb0 ^ r0));
            cnt += __popc(mm);
        }
    }
    return cnt;
}

// pick the bin containing rank for each branch; update ranks; return digits+counts
__device__ __forceinline__ void pick_bins(int cnt, int& rank1, int& rank2,
                                          unsigned& dig1, unsigned& dig2,
                                          int& m1, int& m2, int lane)
{
    int incl = cnt;
    #pragma unroll
    for (int o = 1; o < 16; o <<= 1) {
        int n = __shfl_up_sync(~0u, incl, o, 16);
        if ((lane & 15) >= o) incl += n;
    }
    int excl = incl - cnt;
    int rk = (lane < 16) ? rank1 : rank2;
    bool hit = (rk >= excl) && (rk < incl);
    unsigned bal = __ballot_sync(~0u, hit);
    int src1 = __ffs(bal & 0xFFFFu) - 1;
    int src2 = 31 - __clz(bal & 0xFFFF0000u);
    int nr = rk - excl;
    dig1 = (unsigned)(src1 & 15);
    dig2 = (unsigned)(src2 & 15);
    rank1 = __shfl_sync(~0u, nr, src1);
    rank2 = __shfl_sync(~0u, nr, src2);
    m1 = __shfl_sync(~0u, cnt, src1);
    m2 = __shfl_sync(~0u, cnt, src2);
}

__device__ __forceinline__ void compact_sweep(const float4* __restrict__ vsrc,
                                              const float* __restrict__ sbias,
                                              unsigned top1, unsigned top2,
                                              unsigned maskTop,
                                              unsigned* l1, unsigned* l2,
                                              bool en1, bool en2, int lane)
{
    int n1 = 0, n2 = 0;
    const unsigned lt = (1u << lane) - 1u;
    const float4* bs4 = (const float4*)sbias;
    for (int t = 0; t < 16; t++) {
        float4 v4 = __ldg(vsrc + t * 32 + lane);
        float4 b4 = bs4[t * 32 + lane];
        #pragma unroll
        for (int e = 0; e < 4; e++) {
            float v = (&v4.x)[e], bb = (&b4.x)[e];
            unsigned u1 = f2u(bb - v), u2 = f2u(bb + v);
            bool k1 = en1 && (((u1 ^ top1) & maskTop) == 0);
            bool k2 = en2 && (((u2 ^ top2) & maskTop) == 0);
            unsigned bal1 = __ballot_sync(~0u, k1);
            if (k1) l1[n1 + __popc(bal1 & lt)] = u1;
            n1 += __popc(bal1);
            unsigned bal2 = __ballot_sync(~0u, k2);
            if (k2) l2[n2 + __popc(bal2 & lt)] = u2;
            n2 += __popc(bal2);
        }
    }
}

// one 4-bit radix pass on a compacted list (shared prefix), in-place compact.
__device__ __forceinline__ unsigned list_pass(unsigned* L, int& m, int& rank,
                                              int shift, int lane)
{
    const unsigned bin = lane & 15;
    const unsigned r0 = (bin & 1) ? ~0u : 0u;
    const unsigned r1 = (bin & 2) ? ~0u : 0u;
    const unsigned r2 = (bin & 4) ? ~0u : 0u;
    const unsigned r3 = (bin & 8) ? ~0u : 0u;
    const unsigned lt = (1u << lane) - 1u;
    int iters = (m + 31) >> 5;
    int cnt = 0;
    for (int i = 0; i < iters; i++) {
        int idx = i * 32 + lane;
        bool act = idx < m;
        unsigned u = act ? L[idx] : 0u;
        unsigned d = u >> shift;
        unsigned B0 = __ballot_sync(~0u, act && (d & 1));
        unsigned B1 = __ballot_sync(~0u, act && (d & 2));
        unsigned B2 = __ballot_sync(~0u, act && (d & 4));
        unsigned B3 = __ballot_sync(~0u, act && (d & 8));
        unsigned A  = __ballot_sync(~0u, act);
        unsigned mm = A & ~((B3 ^ r3) | (B2 ^ r2) | (B1 ^ r1) | (B0 ^ r0));
        cnt += __popc(mm);
    }
    int incl = cnt;
    #pragma unroll
    for (int o = 1; o < 16; o <<= 1) {
        int n = __shfl_up_sync(~0u, incl, o, 16);
        if ((lane & 15) >= o) incl += n;
    }
    int excl = incl - cnt;
    bool hit = (lane < 16) && (rank >= excl) && (rank < incl);
    unsigned bal = __ballot_sync(~0u, hit);
    int src = __ffs(bal) - 1;
    unsigned dig = (unsigned)src;
    int nr = rank - excl;
    rank = __shfl_sync(~0u, nr, src);
    // in-place compact (write idx <= read idx, processed in order)
    int w = 0;
    for (int i = 0; i < iters; i++) {
        int idx = i * 32 + lane;
        bool act = idx < m;
        unsigned u = act ? L[idx] : 0u;
        bool keep = act && (((u >> shift) & 15u) == dig);
        unsigned kb = __ballot_sync(~0u, keep);
        if (keep) L[w + __popc(kb & lt)] = u;
        w += __popc(kb);
    }
    m = w;
    return dig;
}

__device__ __forceinline__ unsigned final32(const unsigned* L, int m, int rank, int lane)
{
    unsigned myv = (lane < m) ? L[lane] : 0xFFFFFFFFu;
    int c = 0;
    #pragma unroll
    for (int j = 0; j < 32; j++) {
        unsigned o = __shfl_sync(~0u, myv, j);
        c += (o < myv) || (o == myv && j < lane);
    }
    bool hit = (c == rank) && (lane < m);
    unsigned bal = __ballot_sync(~0u, hit);
    int src = __ffs(bal) - 1;
    return __shfl_sync(~0u, myv, src);
}

#define SEL_SMEM (2048 * 4 + 4 * 2 * SEL_CAP * 4)

__global__ void __launch_bounds__(128) select_kernel(const float* __restrict__ bias)
{
    extern __shared__ float smem[];
    float* sbias = smem;                          // 2048 floats
    unsigned* slist = (unsigned*)(smem + 2048);   // 4 warps * 2 * SEL_CAP

    const int tid = threadIdx.x;
    const int wid = tid >> 5, lane = tid & 31;

    {
        const float4* bsrc = (const float4*)bias;
        float4* bdst = (float4*)sbias;
        #pragma unroll
        for (int i = 0; i < 4; i++) bdst[tid + 128 * i] = bsrc[tid + 128 * i];
    }
    __syncthreads();

    const int pos = blockIdx.x * 4 + wid;
    const float4* vsrc = (const float4*)(g_conv + (size_t)pos * NC);
    unsigned* l1 = slist + wid * 2 * SEL_CAP;
    unsigned* l2 = l1 + SEL_CAP;

    int rank1 = KSEL, rank2 = KSEL;
    unsigned top1 = 0, top2 = 0, maskTop = 0;
    int m1 = NC, m2 = NC;
    int shift = 28;
    unsigned dig1, dig2;

    // pass 0 (unmasked)
    {
        int cnt = hist_sweep<false>(vsrc, sbias, 0, 0, 0, shift, lane);
        pick_bins(cnt, rank1, rank2, dig1, dig2, m1, m2, lane);
        top1 |= dig1 << shift; top2 |= dig2 << shift;
        maskTop |= 0xFu << shift; shift -= 4;
    }
    // masked passes until both candidate sets fit in the lists
    while ((m1 > SEL_CAP || m2 > SEL_CAP) && shift >= 0) {
        int cnt = hist_sweep<true>(vsrc, sbias, top1, top2, maskTop, shift, lane);
        pick_bins(cnt, rank1, rank2, dig1, dig2, m1, m2, lane);
        top1 |= dig1 << shift; top2 |= dig2 << shift;
        maskTop |= 0xFu << shift; shift -= 4;
    }

    bool en1 = (m1 <= SEL_CAP), en2 = (m2 <= SEL_CAP);
    compact_sweep(vsrc, sbias, top1, top2, maskTop, l1, l2, en1, en2, lane);

    unsigned ansu1, ansu2;
    {   // branch 1
        if (!en1) ansu1 = top1;          // degenerate: prefix fully determined
        else {
            int sh = shift, m = m1, r = rank1; unsigned tp = top1;
            while (m > 32 && sh >= 0) { unsigned d = list_pass(l1, m, r, sh, lane); tp |= d << sh; sh -= 4; }
            ansu1 = (m > 32) ? tp : final32(l1, m, r, lane);
        }
    }
    {   // branch 2
        if (!en2) ansu2 = top2;
        else {
            int sh = shift, m = m2, r = rank2; unsigned tp = top2;
            while (m > 32 && sh >= 0) { unsigned d = list_pass(l2, m, r, sh, lane); tp |= d << sh; sh -= 4; }
            ansu2 = (m > 32) ? tp : final32(l2, m, r, lane);
        }
    }

    if (lane == 0) {
        g_t1[pos] = u2f(ansu1);
        g_t2[pos] = u2f(ansu2);
    }
}

// ---------------------------------------------------------------------------
// Kernel 3: masks + (avg_pool_ceil(5,3) o adaptive(6)) as separable 6x27 map A.
// ---------------------------------------------------------------------------
__global__ void __launch_bounds__(128) pool_kernel(const float* __restrict__ bias,
                                                   float* __restrict__ out)
{
    __shared__ float st1[NPOS9], st2[NPOS9];
    __shared__ float sA[6][28];

    const int b = blockIdx.y;
    const int c = blockIdx.x * 128 + threadIdx.x;

    for (int i = threadIdx.x; i < NPOS9; i += 128) {
        st1[i] = g_t1[b * NPOS9 + i];
        st2[i] = g_t2[b * NPOS9 + i];
    }
    if (threadIdx.x < 27) {
        int wcol = threadIdx.x;
        const int sidx[6] = {0, 1, 3, 4, 6, 7};
        #pragma unroll
        for (int i = 0; i < 6; i++) {
            float a = 0.0f;
            #pragma unroll
            for (int q = 0; q < 2; q++) {
                int p = sidx[i] + q;
                int st = 3 * p, en = (st + 5 < 27) ? st + 5 : 27;
                if (wcol >= st && wcol < en) a += 0.5f / (float)(en - st);
            }
            sA[i][wcol] = a;
        }
    }
    __syncthreads();

    const float bc = bias[c];
    const float* p = g_conv + (size_t)b * NPOS9 * NC + c;

    float acc1[36], acc2[36];
    #pragma unroll
    for (int k = 0; k < 36; k++) { acc1[k] = 0.0f; acc2[k] = 0.0f; }

    int idx = 0;
    for (int h = 0; h < 27; h++) {
        float r1[6], r2[6];
        #pragma unroll
        for (int j = 0; j < 6; j++) { r1[j] = 0.0f; r2[j] = 0.0f; }
        for (int wcol = 0; wcol < 27; wcol++, idx++) {
            float v = __ldg(p + (size_t)idx * NC);
            float m1 = (bc - v < st1[idx]) ? 1.0f : 0.0f;
            float m2 = (bc + v < st2[idx]) ? 1.0f : 0.0f;
            #pragma unroll
            for (int j = 0; j < 6; j++) {
                float a = sA[j][wcol];
                r1[j] += a * m1;
                r2[j] += a * m2;
            }
        }
        #pragma unroll
        for (int i = 0; i < 6; i++) {
            float ah = sA[i][h];
            #pragma unroll
            for (int j = 0; j < 6; j++) {
                acc1[i * 6 + j] += ah * r1[j];
                acc2[i * 6 + j] += ah * r2[j];
            }
        }
    }

    float* o1 = out + ((size_t)(b * NC + c)) * 36;
    float* o2 = o1 + (size_t)NB * NC * 36;
    #pragma unroll
    for (int k = 0; k < 36; k++) { o1[k] = acc1[k]; o2[k] = acc2[k]; }
}

// ---------------------------------------------------------------------------
extern "C" void kernel_launch(void* const* d_in, const int* in_sizes, int n_in,
                              void* d_out, int out_size)
{
    const float* x    = (const float*)d_in[0]; // [64,3,32,32]
    const float* w    = (const float*)d_in[1]; // [2048,3,6,6]
    const float* bias = (const float*)d_in[2]; // [2048]
    float* out = (float*)d_out;                // [2][64,2048,6,6]

    cudaFuncSetAttribute(conv_kernel, cudaFuncAttributeMaxDynamicSharedMemorySize, CONV_SMEM);
    cudaFuncSetAttribute(select_kernel, cudaFuncAttributeMaxDynamicSharedMemorySize, SEL_SMEM);

    conv_kernel<<<dim3(16, 64), 256, CONV_SMEM>>>(x, w);
    select_kernel<<<TOTPOS / 4, 128, SEL_SMEM>>>(bias);
    pool_kernel<<<dim3(16, 64), 128>>>(bias, out);
}

// round 5
// speedup vs baseline: 3.6181x; 1.0097x over previous
#include <cuda_runtime.h>
#include <cstdint>

#define NB 64
#define NC 2048
#define NPOS9 729          // 27*27
#define TOTPOS (NB*NPOS9)  // 46656
#define KSEL 819
#define SEL_CAP 1536

__device__ float g_conv[(size_t)NB * NPOS9 * NC];  // NHWC: [b][p][c]
__device__ float g_t1[TOTPOS];
__device__ float g_t2[TOTPOS];

// ---------------------------------------------------------------------------
// Kernel 1: conv (VALID, stride 1) -> NHWC scratch.  fp32 via fma.rn.f32x2.
// smem: xs2 = duplicated {x,x} u64 (24576B), ws64 = paired weights (55296B)
// ws64 layout: [(k*4+q)*16 + ch_tid] -> channels (ch_tid*8+2q, ch_tid*8+2q+1)
// => one LDS.64 per pair: lanes 0-15 hit words 2L,2L+1 = all 32 banks once.
// ---------------------------------------------------------------------------
#define CONV_XS2_U64 3072
#define CONV_W_U64  (108 * 4 * 16)
#define CONV_SMEM ((CONV_XS2_U64 + CONV_W_U64) * 8)

__global__ void __launch_bounds__(256) conv_kernel(const float* __restrict__ x,
                                                   const float* __restrict__ w)
{
    extern __shared__ unsigned long long smem64[];
    float2* xs2 = (float2*)smem64;                       // 3072 pairs {x,x}
    float2* ws2 = (float2*)(smem64 + CONV_XS2_U64);      // 6912 weight pairs
    const unsigned long long* xsu = smem64;
    const unsigned long long* wsu = smem64 + CONV_XS2_U64;

    const int b = blockIdx.y;
    const int c0 = blockIdx.x * 128;
    const int tid = threadIdx.x;

    // x: duplicate each value into a u64 pair
    {
        const float* xsrc = x + (size_t)b * 3072;
        #pragma unroll
        for (int i = 0; i < 12; i++) {
            int idx = tid + 256 * i;
            float v = xsrc[idx];
            xs2[idx] = make_float2(v, v);
        }
    }
    // weights: paired, transposed to conflict-free layout
    for (int idx = tid; idx < CONV_W_U64; idx += 256) {
        int ct = idx & 15;
        int kq = idx >> 4;
        int k = kq >> 2, q = kq & 3;
        int ch = c0 + ct * 8 + 2 * q;
        float a = w[(size_t)ch * 108 + k];
        float bb = w[(size_t)(ch + 1) * 108 + k];
        ws2[idx] = make_float2(a, bb);
    }
    __syncthreads();

    const int ch_tid = tid & 15;
    const int pos_tid = tid >> 4;
    const int ch0 = ch_tid * 8;

    for (int chunk = 0; chunk < 6; chunk++) {
        const int p0 = chunk * 128 + pos_tid * 8;
        int pbase[8];
        #pragma unroll
        for (int pp = 0; pp < 8; pp++) {
            int p = p0 + pp; if (p > 728) p = 728;
            int y = p / 27;
            pbase[pp] = y * 32 + (p - y * 27);
        }
        unsigned long long acc0[8], acc1[8], acc2[8], acc3[8];
        #pragma unroll
        for (int pp = 0; pp < 8; pp++) { acc0[pp] = 0ull; acc1[pp] = 0ull; acc2[pp] = 0ull; acc3[pp] = 0ull; }

        #pragma unroll 1
        for (int c = 0; c < 3; c++) {
            #pragma unroll 1
            for (int i = 0; i < 6; i++) {
                const unsigned long long* xrow = xsu + c * 1024 + i * 32;
                const int kbase = (c * 36 + i * 6) * 4;
                #pragma unroll
                for (int j = 0; j < 6; j++) {
                    const unsigned long long* wk = wsu + (size_t)(kbase + j * 4) * 16 + ch_tid;
                    unsigned long long w0 = wk[0], w1 = wk[16], w2 = wk[32], w3 = wk[48];
                    #pragma unroll
                    for (int pp = 0; pp < 8; pp++) {
                        unsigned long long xx = xrow[pbase[pp] + j];
                        asm("fma.rn.f32x2 %0, %1, %2, %0;" : "+l"(acc0[pp]) : "l"(w0), "l"(xx));
                        asm("fma.rn.f32x2 %0, %1, %2, %0;" : "+l"(acc1[pp]) : "l"(w1), "l"(xx));
                        asm("fma.rn.f32x2 %0, %1, %2, %0;" : "+l"(acc2[pp]) : "l"(w2), "l"(xx));
                        asm("fma.rn.f32x2 %0, %1, %2, %0;" : "+l"(acc3[pp]) : "l"(w3), "l"(xx));
                    }
                }
            }
        }
        #pragma unroll
        for (int pp = 0; pp < 8; pp++) {
            int p = p0 + pp;
            if (p < 729) {
                float* dst = g_conv + ((size_t)(b * NPOS9 + p)) * NC + c0 + ch0;
                float a, bb, cc, dd, e, f, g, h;
                asm("mov.b64 {%0, %1}, %2;" : "=f"(a), "=f"(bb) : "l"(acc0[pp]));
                asm("mov.b64 {%0, %1}, %2;" : "=f"(cc), "=f"(dd) : "l"(acc1[pp]));
                asm("mov.b64 {%0, %1}, %2;" : "=f"(e), "=f"(f) : "l"(acc2[pp]));
                asm("mov.b64 {%0, %1}, %2;" : "=f"(g), "=f"(h) : "l"(acc3[pp]));
                ((float4*)dst)[0] = make_float4(a, bb, cc, dd);
                ((float4*)dst)[1] = make_float4(e, f, g, h);
            }
        }
    }
}

// ---------------------------------------------------------------------------
// Kernel 2: atomic-free radix select via ballot-transpose histograms.
// One warp per position; both branches (bias-v, bias+v) fused per sweep.
// ---------------------------------------------------------------------------
__device__ __forceinline__ unsigned f2u(float f) {
    int b = __float_as_int(f);
    return (unsigned)(b ^ ((b >> 31) | 0x80000000));
}
__device__ __forceinline__ float u2f(unsigned u) {
    unsigned b = (u & 0x80000000u) ? (u & 0x7fffffffu) : ~u;
    return __uint_as_float(b);
}

template<bool MASKED>
__device__ __forceinline__ int hist_sweep(const float4* __restrict__ vsrc,
                                          const float* __restrict__ sbias,
                                          unsigned top1, unsigned top2,
                                          unsigned maskTop, int shift, int lane)
{
    const unsigned bin = lane & 15;
    const unsigned r0 = (bin & 1) ? ~0u : 0u;
    const unsigned r1 = (bin & 2) ? ~0u : 0u;
    const unsigned r2 = (bin & 4) ? ~0u : 0u;
    const unsigned r3 = (bin & 8) ? ~0u : 0u;
    const bool br2 = (lane >= 16);
    int cnt = 0;
    const float4* bs4 = (const float4*)sbias;
    for (int t = 0; t < 16; t++) {
        float4 v4 = __ldg(vsrc + t * 32 + lane);
        float4 b4 = bs4[t * 32 + lane];
        #pragma unroll
        for (int e = 0; e < 4; e++) {
            float v = (&v4.x)[e], bb = (&b4.x)[e];
            unsigned u1 = f2u(bb - v), u2 = f2u(bb + v);
            bool a1 = MASKED ? (((u1 ^ top1) & maskTop) == 0) : true;
            bool a2 = MASKED ? (((u2 ^ top2) & maskTop) == 0) : true;
            unsigned d1 = u1 >> shift, d2 = u2 >> shift;
            unsigned B10 = __ballot_sync(~0u, a1 && (d1 & 1));
            unsigned B11 = __ballot_sync(~0u, a1 && (d1 & 2));
            unsigned B12 = __ballot_sync(~0u, a1 && (d1 & 4));
            unsigned B13 = __ballot_sync(~0u, a1 && (d1 & 8));
            unsigned A1  = MASKED ? __ballot_sync(~0u, a1) : ~0u;
            unsigned B20 = __ballot_sync(~0u, a2 && (d2 & 1));
            unsigned B21 = __ballot_sync(~0u, a2 && (d2 & 2));
            unsigned B22 = __ballot_sync(~0u, a2 && (d2 & 4));
            unsigned B23 = __ballot_sync(~0u, a2 && (d2 & 8));
            unsigned A2  = MASKED ? __ballot_sync(~0u, a2) : ~0u;
            unsigned Bb0 = br2 ? B20 : B10;
            unsigned Bb1 = br2 ? B21 : B11;
            unsigned Bb2 = br2 ? B22 : B12;
            unsigned Bb3 = br2 ? B23 : B13;
            unsigned A   = br2 ? A2  : A1;
            unsigned mm = A & ~((Bb3 ^ r3) | (Bb2 ^ r2) | (Bb1 ^ r1) | (Bb0 ^ r0));
            cnt += __popc(mm);
        }
    }
    return cnt;
}

__device__ __forceinline__ void pick_bins(int cnt, int& rank1, int& rank2,
                                          unsigned& dig1, unsigned& dig2,
                                          int& m1, int& m2, int lane)
{
    int incl = cnt;
    #pragma unroll
    for (int o = 1; o < 16; o <<= 1) {
        int n = __shfl_up_sync(~0u, incl, o, 16);
        if ((lane & 15) >= o) incl += n;
    }
    int excl = incl - cnt;
    int rk = (lane < 16) ? rank1 : rank2;
    bool hit = (rk >= excl) && (rk < incl);
    unsigned bal = __ballot_sync(~0u, hit);
    int src1 = __ffs(bal & 0xFFFFu) - 1;
    int src2 = 31 - __clz(bal & 0xFFFF0000u);
    int nr = rk - excl;
    dig1 = (unsigned)(src1 & 15);
    dig2 = (unsigned)(src2 & 15);
    rank1 = __shfl_sync(~0u, nr, src1);
    rank2 = __shfl_sync(~0u, nr, src2);
    m1 = __shfl_sync(~0u, cnt, src1);
    m2 = __shfl_sync(~0u, cnt, src2);
}

__device__ __forceinline__ void compact_sweep(const float4* __restrict__ vsrc,
                                              const float* __restrict__ sbias,
                                              unsigned top1, unsigned top2,
                                              unsigned maskTop,
                                              unsigned* l1, unsigned* l2,
                                              bool en1, bool en2, int lane)
{
    int n1 = 0, n2 = 0;
    const unsigned lt = (1u << lane) - 1u;
    const float4* bs4 = (const float4*)sbias;
    for (int t = 0; t < 16; t++) {
        float4 v4 = __ldg(vsrc + t * 32 + lane);
        float4 b4 = bs4[t * 32 + lane];
        #pragma unroll
        for (int e = 0; e < 4; e++) {
            float v = (&v4.x)[e], bb = (&b4.x)[e];
            unsigned u1 = f2u(bb - v), u2 = f2u(bb + v);
            bool k1 = en1 && (((u1 ^ top1) & maskTop) == 0);
            bool k2 = en2 && (((u2 ^ top2) & maskTop) == 0);
            unsigned bal1 = __ballot_sync(~0u, k1);
            if (k1) l1[n1 + __popc(bal1 & lt)] = u1;
            n1 += __popc(bal1);
            unsigned bal2 = __ballot_sync(~0u, k2);
            if (k2) l2[n2 + __popc(bal2 & lt)] = u2;
            n2 += __popc(bal2);
        }
    }
}

__device__ __forceinline__ unsigned list_pass(unsigned* L, int& m, int& rank,
                                              int shift, int lane)
{
    const unsigned bin = lane & 15;
    const unsigned r0 = (bin & 1) ? ~0u : 0u;
    const unsigned r1 = (bin & 2) ? ~0u : 0u;
    const unsigned r2 = (bin & 4) ? ~0u : 0u;
    const unsigned r3 = (bin & 8) ? ~0u : 0u;
    const unsigned lt = (1u << lane) - 1u;
    int iters = (m + 31) >> 5;
    int cnt = 0;
    for (int i = 0; i < iters; i++) {
        int idx = i * 32 + lane;
        bool act = idx < m;
        unsigned u = act ? L[idx] : 0u;
        unsigned d = u >> shift;
        unsigned B0 = __ballot_sync(~0u, act && (d & 1));
        unsigned B1 = __ballot_sync(~0u, act && (d & 2));
        unsigned B2 = __ballot_sync(~0u, act && (d & 4));
        unsigned B3 = __ballot_sync(~0u, act && (d & 8));
        unsigned A  = __ballot_sync(~0u, act);
        unsigned mm = A & ~((B3 ^ r3) | (B2 ^ r2) | (B1 ^ r1) | (B0 ^ r0));
        cnt += __popc(mm);
    }
    int incl = cnt;
    #pragma unroll
    for (int o = 1; o < 16; o <<= 1) {
        int n = __shfl_up_sync(~0u, incl, o, 16);
        if ((lane & 15) >= o) incl += n;
    }
    int excl = incl - cnt;
    bool hit = (lane < 16) && (rank >= excl) && (rank < incl);
    unsigned bal = __ballot_sync(~0u, hit);
    int src = __ffs(bal) - 1;
    unsigned dig = (unsigned)src;
    int nr = rank - excl;
    rank = __shfl_sync(~0u, nr, src);
    int w = 0;
    for (int i = 0; i < iters; i++) {
        int idx = i * 32 + lane;
        bool act = idx < m;
        unsigned u = act ? L[idx] : 0u;
        bool keep = act && (((u >> shift) & 15u) == dig);
        unsigned kb = __ballot_sync(~0u, keep);
        if (keep) L[w + __popc(kb & lt)] = u;
        w += __popc(kb);
    }
    m = w;
    return dig;
}

__device__ __forceinline__ unsigned final32(const unsigned* L, int m, int rank, int lane)
{
    unsigned myv = (lane < m) ? L[lane] : 0xFFFFFFFFu;
    int c = 0;
    #pragma unroll
    for (int j = 0; j < 32; j++) {
        unsigned o = __shfl_sync(~0u, myv, j);
        c += (o < myv) || (o == myv && j < lane);
    }
    bool hit = (c == rank) && (lane < m);
    unsigned bal = __ballot_sync(~0u, hit);
    int src = __ffs(bal) - 1;
    return __shfl_sync(~0u, myv, src);
}

#define SEL_SMEM (2048 * 4 + 4 * 2 * SEL_CAP * 4)

__global__ void __launch_bounds__(128) select_kernel(const float* __restrict__ bias)
{
    extern __shared__ float smem[];
    float* sbias = smem;                          // 2048 floats
    unsigned* slist = (unsigned*)(smem + 2048);   // 4 warps * 2 * SEL_CAP

    const int tid = threadIdx.x;
    const int wid = tid >> 5, lane = tid & 31;

    {
        const float4* bsrc = (const float4*)bias;
        float4* bdst = (float4*)sbias;
        #pragma unroll
        for (int i = 0; i < 4; i++) bdst[tid + 128 * i] = bsrc[tid + 128 * i];
    }
    __syncthreads();

    const int pos = blockIdx.x * 4 + wid;
    const float4* vsrc = (const float4*)(g_conv + (size_t)pos * NC);
    unsigned* l1 = slist + wid * 2 * SEL_CAP;
    unsigned* l2 = l1 + SEL_CAP;

    int rank1 = KSEL, rank2 = KSEL;
    unsigned top1 = 0, top2 = 0, maskTop = 0;
    int m1 = NC, m2 = NC;
    int shift = 28;
    unsigned dig1, dig2;

    {
        int cnt = hist_sweep<false>(vsrc, sbias, 0, 0, 0, shift, lane);
        pick_bins(cnt, rank1, rank2, dig1, dig2, m1, m2, lane);
        top1 |= dig1 << shift; top2 |= dig2 << shift;
        maskTop |= 0xFu << shift; shift -= 4;
    }
    while ((m1 > SEL_CAP || m2 > SEL_CAP) && shift >= 0) {
        int cnt = hist_sweep<true>(vsrc, sbias, top1, top2, maskTop, shift, lane);
        pick_bins(cnt, rank1, rank2, dig1, dig2, m1, m2, lane);
        top1 |= dig1 << shift; top2 |= dig2 << shift;
        maskTop |= 0xFu << shift; shift -= 4;
    }

    bool en1 = (m1 <= SEL_CAP), en2 = (m2 <= SEL_CAP);
    compact_sweep(vsrc, sbias, top1, top2, maskTop, l1, l2, en1, en2, lane);

    unsigned ansu1, ansu2;
    {
        if (!en1) ansu1 = top1;
        else {
            int sh = shift, m = m1, r = rank1; unsigned tp = top1;
            while (m > 32 && sh >= 0) { unsigned d = list_pass(l1, m, r, sh, lane); tp |= d << sh; sh -= 4; }
            ansu1 = (m > 32) ? tp : final32(l1, m, r, lane);
        }
    }
    {
        if (!en2) ansu2 = top2;
        else {
            int sh = shift, m = m2, r = rank2; unsigned tp = top2;
            while (m > 32 && sh >= 0) { unsigned d = list_pass(l2, m, r, sh, lane); tp |= d << sh; sh -= 4; }
            ansu2 = (m > 32) ? tp : final32(l2, m, r, lane);
        }
    }

    if (lane == 0) {
        g_t1[pos] = u2f(ansu1);
        g_t2[pos] = u2f(ansu2);
    }
}

// ---------------------------------------------------------------------------
// Kernel 3: masks + (avg_pool_ceil(5,3) o adaptive(6)) as separable 6x27 map A.
// ---------------------------------------------------------------------------
__global__ void __launch_bounds__(128) pool_kernel(const float* __restrict__ bias,
                                                   float* __restrict__ out)
{
    __shared__ float st1[NPOS9], st2[NPOS9];
    __shared__ float sA[6][28];

    const int b = blockIdx.y;
    const int c = blockIdx.x * 128 + threadIdx.x;

    for (int i = threadIdx.x; i < NPOS9; i += 128) {
        st1[i] = g_t1[b * NPOS9 + i];
        st2[i] = g_t2[b * NPOS9 + i];
    }
    if (threadIdx.x < 27) {
        int wcol = threadIdx.x;
        const int sidx[6] = {0, 1, 3, 4, 6, 7};
        #pragma unroll
        for (int i = 0; i < 6; i++) {
            float a = 0.0f;
            #pragma unroll
            for (int q = 0; q < 2; q++) {
                int p = sidx[i] + q;
                int st = 3 * p, en = (st + 5 < 27) ? st + 5 : 27;
                if (wcol >= st && wcol < en) a += 0.5f / (float)(en - st);
            }
            sA[i][wcol] = a;
        }
    }
    __syncthreads();

    const float bc = bias[c];
    const float* p = g_conv + (size_t)b * NPOS9 * NC + c;

    float acc1[36], acc2[36];
    #pragma unroll
    for (int k = 0; k < 36; k++) { acc1[k] = 0.0f; acc2[k] = 0.0f; }

    int idx = 0;
    for (int h = 0; h < 27; h++) {
        float r1[6], r2[6];
        #pragma unroll
        for (int j = 0; j < 6; j++) { r1[j] = 0.0f; r2[j] = 0.0f; }
        for (int wcol = 0; wcol < 27; wcol++, idx++) {
            float v = __ldg(p + (size_t)idx * NC);
            float m1 = (bc - v < st1[idx]) ? 1.0f : 0.0f;
            float m2 = (bc + v < st2[idx]) ? 1.0f : 0.0f;
            #pragma unroll
            for (int j = 0; j < 6; j++) {
                float a = sA[j][wcol];
                r1[j] += a * m1;
                r2[j] += a * m2;
            }
        }
        #pragma unroll
        for (int i = 0; i < 6; i++) {
            float ah = sA[i][h];
            #pragma unroll
            for (int j = 0; j < 6; j++) {
                acc1[i * 6 + j] += ah * r1[j];
                acc2[i * 6 + j] += ah * r2[j];
            }
        }
    }

    float* o1 = out + ((size_t)(b * NC + c)) * 36;
    float* o2 = o1 + (size_t)NB * NC * 36;
    #pragma unroll
    for (int k = 0; k < 36; k++) { o1[k] = acc1[k]; o2[k] = acc2[k]; }
}

// ---------------------------------------------------------------------------
extern "C" void kernel_launch(void* const* d_in, const int* in_sizes, int n_in,
                              void* d_out, int out_size)
{
    const float* x    = (const float*)d_in[0]; // [64,3,32,32]
    const float* w    = (const float*)d_in[1]; // [2048,3,6,6]
    const float* bias = (const float*)d_in[2]; // [2048]
    float* out = (float*)d_out;                // [2][64,2048,6,6]

    cudaFuncSetAttribute(conv_kernel, cudaFuncAttributeMaxDynamicSharedMemorySize, CONV_SMEM);
    cudaFuncSetAttribute(select_kernel, cudaFuncAttributeMaxDynamicSharedMemorySize, SEL_SMEM);

    conv_kernel<<<dim3(16, 64), 256, CONV_SMEM>>>(x, w);
    select_kernel<<<TOTPOS / 4, 128, SEL_SMEM>>>(bias);
    pool_kernel<<<dim3(16, 64), 128>>>(bias, out);
}

// round 6
// speedup vs baseline: 3.9747x; 1.0986x over previous
#include <cuda_runtime.h>
#include <cstdint>

#define NB 64
#define NC 2048
#define NPOS9 729          // 27*27
#define TOTPOS (NB*NPOS9)  // 46656
#define KSEL 819
#define SEL_CAP 1024

__device__ float g_conv[(size_t)NB * NPOS9 * NC];  // NHWC: [b][p][c]
__device__ float g_t1[TOTPOS];
__device__ float g_t2[TOTPOS];

// ---------------------------------------------------------------------------
// Kernel 1: conv (VALID, stride 1) -> NHWC scratch.  fp32 via fma.rn.f32x2.
// ---------------------------------------------------------------------------
#define CONV_XS2_U64 3072
#define CONV_W_U64  (108 * 4 * 16)
#define CONV_SMEM ((CONV_XS2_U64 + CONV_W_U64) * 8)

__global__ void __launch_bounds__(256) conv_kernel(const float* __restrict__ x,
                                                   const float* __restrict__ w)
{
    extern __shared__ unsigned long long smem64[];
    float2* xs2 = (float2*)smem64;                       // 3072 pairs {x,x}
    float2* ws2 = (float2*)(smem64 + CONV_XS2_U64);      // 6912 weight pairs
    const unsigned long long* xsu = smem64;
    const unsigned long long* wsu = smem64 + CONV_XS2_U64;

    const int b = blockIdx.y;
    const int c0 = blockIdx.x * 128;
    const int tid = threadIdx.x;

    {
        const float* xsrc = x + (size_t)b * 3072;
        #pragma unroll
        for (int i = 0; i < 12; i++) {
            int idx = tid + 256 * i;
            float v = xsrc[idx];
            xs2[idx] = make_float2(v, v);
        }
    }
    for (int idx = tid; idx < CONV_W_U64; idx += 256) {
        int ct = idx & 15;
        int kq = idx >> 4;
        int k = kq >> 2, q = kq & 3;
        int ch = c0 + ct * 8 + 2 * q;
        float a = w[(size_t)ch * 108 + k];
        float bb = w[(size_t)(ch + 1) * 108 + k];
        ws2[idx] = make_float2(a, bb);
    }
    __syncthreads();

    const int ch_tid = tid & 15;
    const int pos_tid = tid >> 4;
    const int ch0 = ch_tid * 8;

    for (int chunk = 0; chunk < 6; chunk++) {
        const int p0 = chunk * 128 + pos_tid * 8;
        int pbase[8];
        #pragma unroll
        for (int pp = 0; pp < 8; pp++) {
            int p = p0 + pp; if (p > 728) p = 728;
            int y = p / 27;
            pbase[pp] = y * 32 + (p - y * 27);
        }
        unsigned long long acc0[8], acc1[8], acc2[8], acc3[8];
        #pragma unroll
        for (int pp = 0; pp < 8; pp++) { acc0[pp] = 0ull; acc1[pp] = 0ull; acc2[pp] = 0ull; acc3[pp] = 0ull; }

        #pragma unroll 1
        for (int c = 0; c < 3; c++) {
            #pragma unroll 1
            for (int i = 0; i < 6; i++) {
                const unsigned long long* xrow = xsu + c * 1024 + i * 32;
                const int kbase = (c * 36 + i * 6) * 4;
                #pragma unroll
                for (int j = 0; j < 6; j++) {
                    const unsigned long long* wk = wsu + (size_t)(kbase + j * 4) * 16 + ch_tid;
                    unsigned long long w0 = wk[0], w1 = wk[16], w2 = wk[32], w3 = wk[48];
                    #pragma unroll
                    for (int pp = 0; pp < 8; pp++) {
                        unsigned long long xx = xrow[pbase[pp] + j];
                        asm("fma.rn.f32x2 %0, %1, %2, %0;" : "+l"(acc0[pp]) : "l"(w0), "l"(xx));
                        asm("fma.rn.f32x2 %0, %1, %2, %0;" : "+l"(acc1[pp]) : "l"(w1), "l"(xx));
                        asm("fma.rn.f32x2 %0, %1, %2, %0;" : "+l"(acc2[pp]) : "l"(w2), "l"(xx));
                        asm("fma.rn.f32x2 %0, %1, %2, %0;" : "+l"(acc3[pp]) : "l"(w3), "l"(xx));
                    }
                }
            }
        }
        #pragma unroll
        for (int pp = 0; pp < 8; pp++) {
            int p = p0 + pp;
            if (p < 729) {
                float* dst = g_conv + ((size_t)(b * NPOS9 + p)) * NC + c0 + ch0;
                float a, bb, cc, dd, e, f, g, h;
                asm("mov.b64 {%0, %1}, %2;" : "=f"(a), "=f"(bb) : "l"(acc0[pp]));
                asm("mov.b64 {%0, %1}, %2;" : "=f"(cc), "=f"(dd) : "l"(acc1[pp]));
                asm("mov.b64 {%0, %1}, %2;" : "=f"(e), "=f"(f) : "l"(acc2[pp]));
                asm("mov.b64 {%0, %1}, %2;" : "=f"(g), "=f"(h) : "l"(acc3[pp]));
                ((float4*)dst)[0] = make_float4(a, bb, cc, dd);
                ((float4*)dst)[1] = make_float4(e, f, g, h);
            }
        }
    }
}

// ---------------------------------------------------------------------------
// Kernel 2: speculative single-sweep select + exact general fallback.
// ---------------------------------------------------------------------------
__device__ __forceinline__ unsigned f2u(float f) {
    int b = __float_as_int(f);
    return (unsigned)(b ^ ((b >> 31) | 0x80000000));
}
__device__ __forceinline__ float u2f(unsigned u) {
    unsigned b = (u & 0x80000000u) ? (u & 0x7fffffffu) : ~u;
    return __uint_as_float(b);
}

template<bool MASKED>
__device__ __forceinline__ int hist_sweep(const float4* __restrict__ vsrc,
                                          const float* __restrict__ sbias,
                                          unsigned top1, unsigned top2,
                                          unsigned maskTop, int shift, int lane)
{
    const unsigned bin = lane & 15;
    const unsigned r0 = (bin & 1) ? ~0u : 0u;
    const unsigned r1 = (bin & 2) ? ~0u : 0u;
    const unsigned r2 = (bin & 4) ? ~0u : 0u;
    const unsigned r3 = (bin & 8) ? ~0u : 0u;
    const bool br2 = (lane >= 16);
    int cnt = 0;
    const float4* bs4 = (const float4*)sbias;
    for (int t = 0; t < 16; t++) {
        float4 v4 = __ldg(vsrc + t * 32 + lane);
        float4 b4 = bs4[t * 32 + lane];
        #pragma unroll
        for (int e = 0; e < 4; e++) {
            float v = (&v4.x)[e], bb = (&b4.x)[e];
            unsigned u1 = f2u(bb - v), u2 = f2u(bb + v);
            bool a1 = MASKED ? (((u1 ^ top1) & maskTop) == 0) : true;
            bool a2 = MASKED ? (((u2 ^ top2) & maskTop) == 0) : true;
            unsigned d1 = u1 >> shift, d2 = u2 >> shift;
            unsigned B10 = __ballot_sync(~0u, a1 && (d1 & 1));
            unsigned B11 = __ballot_sync(~0u, a1 && (d1 & 2));
            unsigned B12 = __ballot_sync(~0u, a1 && (d1 & 4));
            unsigned B13 = __ballot_sync(~0u, a1 && (d1 & 8));
            unsigned A1  = MASKED ? __ballot_sync(~0u, a1) : ~0u;
            unsigned B20 = __ballot_sync(~0u, a2 && (d2 & 1));
            unsigned B21 = __ballot_sync(~0u, a2 && (d2 & 2));
            unsigned B22 = __ballot_sync(~0u, a2 && (d2 & 4));
            unsigned B23 = __ballot_sync(~0u, a2 && (d2 & 8));
            unsigned A2  = MASKED ? __ballot_sync(~0u, a2) : ~0u;
            unsigned Bb0 = br2 ? B20 : B10;
            unsigned Bb1 = br2 ? B21 : B11;
            unsigned Bb2 = br2 ? B22 : B12;
            unsigned Bb3 = br2 ? B23 : B13;
            unsigned A   = br2 ? A2  : A1;
            unsigned mm = A & ~((Bb3 ^ r3) | (Bb2 ^ r2) | (Bb1 ^ r1) | (Bb0 ^ r0));
            cnt += __popc(mm);
        }
    }
    return cnt;
}

__device__ __forceinline__ void pick_bins(int cnt, int& rank1, int& rank2,
                                          unsigned& dig1, unsigned& dig2,
                                          int& m1, int& m2, int lane)
{
    int incl = cnt;
    #pragma unroll
    for (int o = 1; o < 16; o <<= 1) {
        int n = __shfl_up_sync(~0u, incl, o, 16);
        if ((lane & 15) >= o) incl += n;
    }
    int excl = incl - cnt;
    int rk = (lane < 16) ? rank1 : rank2;
    bool hit = (rk >= excl) && (rk < incl);
    unsigned bal = __ballot_sync(~0u, hit);
    int src1 = __ffs(bal & 0xFFFFu) - 1;
    int src2 = 31 - __clz(bal & 0xFFFF0000u);
    int nr = rk - excl;
    dig1 = (unsigned)(src1 & 15);
    dig2 = (unsigned)(src2 & 15);
    rank1 = __shfl_sync(~0u, nr, src1);
    rank2 = __shfl_sync(~0u, nr, src2);
    m1 = __shfl_sync(~0u, cnt, src1);
    m2 = __shfl_sync(~0u, cnt, src2);
}

__device__ __forceinline__ void compact_sweep(const float4* __restrict__ vsrc,
                                              const float* __restrict__ sbias,
                                              unsigned top1, unsigned top2,
                                              unsigned maskTop,
                                              unsigned* l1, unsigned* l2,
                                              bool en1, bool en2, int lane)
{
    int n1 = 0, n2 = 0;
    const unsigned lt = (1u << lane) - 1u;
    const float4* bs4 = (const float4*)sbias;
    for (int t = 0; t < 16; t++) {
        float4 v4 = __ldg(vsrc + t * 32 + lane);
        float4 b4 = bs4[t * 32 + lane];
        #pragma unroll
        for (int e = 0; e < 4; e++) {
            float v = (&v4.x)[e], bb = (&b4.x)[e];
            unsigned u1 = f2u(bb - v), u2 = f2u(bb + v);
            bool k1 = en1 && (((u1 ^ top1) & maskTop) == 0);
            bool k2 = en2 && (((u2 ^ top2) & maskTop) == 0);
            unsigned bal1 = __ballot_sync(~0u, k1);
            if (k1) l1[n1 + __popc(bal1 & lt)] = u1;
            n1 += __popc(bal1);
            unsigned bal2 = __ballot_sync(~0u, k2);
            if (k2) l2[n2 + __popc(bal2 & lt)] = u2;
            n2 += __popc(bal2);
        }
    }
}

__device__ __forceinline__ unsigned list_pass(unsigned* L, int& m, int& rank,
                                              int shift, int lane)
{
    const unsigned bin = lane & 15;
    const unsigned r0 = (bin & 1) ? ~0u : 0u;
    const unsigned r1 = (bin & 2) ? ~0u : 0u;
    const unsigned r2 = (bin & 4) ? ~0u : 0u;
    const unsigned r3 = (bin & 8) ? ~0u : 0u;
    const unsigned lt = (1u << lane) - 1u;
    int iters = (m + 31) >> 5;
    int cnt = 0;
    for (int i = 0; i < iters; i++) {
        int idx = i * 32 + lane;
        bool act = idx < m;
        unsigned u = act ? L[idx] : 0u;
        unsigned d = u >> shift;
        unsigned B0 = __ballot_sync(~0u, act && (d & 1));
        unsigned B1 = __ballot_sync(~0u, act && (d & 2));
        unsigned B2 = __ballot_sync(~0u, act && (d & 4));
        unsigned B3 = __ballot_sync(~0u, act && (d & 8));
        unsigned A  = __ballot_sync(~0u, act);
        unsigned mm = A & ~((B3 ^ r3) | (B2 ^ r2) | (B1 ^ r1) | (B0 ^ r0));
        cnt += __popc(mm);
    }
    int incl = cnt;
    #pragma unroll
    for (int o = 1; o < 16; o <<= 1) {
        int n = __shfl_up_sync(~0u, incl, o, 16);
        if ((lane & 15) >= o) incl += n;
    }
    int excl = incl - cnt;
    bool hit = (lane < 16) && (rank >= excl) && (rank < incl);
    unsigned bal = __ballot_sync(~0u, hit);
    int src = __ffs(bal) - 1;
    unsigned dig = (unsigned)src;
    int nr = rank - excl;
    rank = __shfl_sync(~0u, nr, src);
    int w = 0;
    for (int i = 0; i < iters; i++) {
        int idx = i * 32 + lane;
        bool act = idx < m;
        unsigned u = act ? L[idx] : 0u;
        bool keep = act && (((u >> shift) & 15u) == dig);
        unsigned kb = __ballot_sync(~0u, keep);
        if (keep) L[w + __popc(kb & lt)] = u;
        w += __popc(kb);
    }
    m = w;
    return dig;
}

__device__ __forceinline__ unsigned final32(const unsigned* L, int m, int rank, int lane)
{
    unsigned myv = (lane < m) ? L[lane] : 0xFFFFFFFFu;
    int c = 0;
    #pragma unroll
    for (int j = 0; j < 32; j++) {
        unsigned o = __shfl_sync(~0u, myv, j);
        c += (o < myv) || (o == myv && j < lane);
    }
    bool hit = (c == rank) && (lane < m);
    unsigned bal = __ballot_sync(~0u, hit);
    int src = __ffs(bal) - 1;
    return __shfl_sync(~0u, myv, src);
}

// solve from a compacted list with known 4-bit top prefix
__device__ __forceinline__ unsigned solve_list(unsigned* L, int m, int rank,
                                               unsigned tp, int sh0, int lane)
{
    int sh = sh0, m_ = m, r = rank; unsigned tp_ = tp;
    while (m_ > 32 && sh >= 0) {
        unsigned d = list_pass(L, m_, r, sh, lane);
        tp_ |= d << sh; sh -= 4;
    }
    return (m_ > 32) ? tp_ : final32(L, m_, r, lane);
}

#define SEL_SMEM (2048 * 4 + 4 * 2 * SEL_CAP * 4)

__global__ void __launch_bounds__(128) select_kernel(const float* __restrict__ bias)
{
    extern __shared__ float smem[];
    float* sbias = smem;                          // 2048 floats
    unsigned* slist = (unsigned*)(smem + 2048);   // 4 warps * 2 * SEL_CAP

    const int tid = threadIdx.x;
    const int wid = tid >> 5, lane = tid & 31;

    {
        const float4* bsrc = (const float4*)bias;
        float4* bdst = (float4*)sbias;
        #pragma unroll
        for (int i = 0; i < 4; i++) bdst[tid + 128 * i] = bsrc[tid + 128 * i];
    }
    __syncthreads();

    const int pos = blockIdx.x * 4 + wid;
    const float4* vsrc = (const float4*)(g_conv + (size_t)pos * NC);
    unsigned* l1 = slist + wid * 2 * SEL_CAP;
    unsigned* l2 = l1 + SEL_CAP;

    // ---- speculative fused sweep: count below bin 4, compact bin 4 ----
    const unsigned lt = (1u << lane) - 1u;
    int cb1 = 0, cb2 = 0;     // # keys < 0x40000000
    int n1 = 0, n2 = 0;       // # keys in [0x40000000, 0x50000000)
    {
        const float4* bs4 = (const float4*)sbias;
        for (int t = 0; t < 16; t++) {
            float4 v4 = __ldg(vsrc + t * 32 + lane);
            float4 b4 = bs4[t * 32 + lane];
            #pragma unroll
            for (int e = 0; e < 4; e++) {
                float v = (&v4.x)[e], bb = (&b4.x)[e];
                unsigned u1 = f2u(bb - v), u2 = f2u(bb + v);
                bool below1 = u1 < 0x40000000u;
                bool in1 = (u1 - 0x40000000u) < 0x10000000u;
                bool below2 = u2 < 0x40000000u;
                bool in2 = (u2 - 0x40000000u) < 0x10000000u;
                cb1 += __popc(__ballot_sync(~0u, below1));
                unsigned bi1 = __ballot_sync(~0u, in1);
                if (in1) { int ix = n1 + __popc(bi1 & lt); if (ix < SEL_CAP) l1[ix] = u1; }
                n1 += __popc(bi1);
                cb2 += __popc(__ballot_sync(~0u, below2));
                unsigned bi2 = __ballot_sync(~0u, in2);
                if (in2) { int ix = n2 + __popc(bi2 & lt); if (ix < SEL_CAP) l2[ix] = u2; }
                n2 += __popc(bi2);
            }
        }
    }
    int r1 = KSEL - cb1, r2 = KSEL - cb2;
    bool ok1 = (r1 >= 0) && (r1 < n1) && (n1 <= SEL_CAP);
    bool ok2 = (r2 >= 0) && (r2 < n2) && (n2 <= SEL_CAP);

    unsigned ansu1, ansu2;
    if (ok1 && ok2) {
        ansu1 = solve_list(l1, n1, r1, 0x40000000u, 24, lane);
        ansu2 = solve_list(l2, n2, r2, 0x40000000u, 24, lane);
    } else {
        // ---- exact general radix path (rare) ----
        int rank1 = KSEL, rank2 = KSEL;
        unsigned top1 = 0, top2 = 0, maskTop = 0;
        int m1 = NC, m2 = NC;
        int shift = 28;
        unsigned dig1, dig2;
        {
            int cnt = hist_sweep<false>(vsrc, sbias, 0, 0, 0, shift, lane);
            pick_bins(cnt, rank1, rank2, dig1, dig2, m1, m2, lane);
            top1 |= dig1 << shift; top2 |= dig2 << shift;
            maskTop |= 0xFu << shift; shift -= 4;
        }
        while ((m1 > SEL_CAP || m2 > SEL_CAP) && shift >= 0) {
            int cnt = hist_sweep<true>(vsrc, sbias, top1, top2, maskTop, shift, lane);
            pick_bins(cnt, rank1, rank2, dig1, dig2, m1, m2, lane);
            top1 |= dig1 << shift; top2 |= dig2 << shift;
            maskTop |= 0xFu << shift; shift -= 4;
        }
        bool en1 = (m1 <= SEL_CAP), en2 = (m2 <= SEL_CAP);
        compact_sweep(vsrc, sbias, top1, top2, maskTop, l1, l2, en1, en2, lane);
        if (!en1) ansu1 = top1;
        else ansu1 = solve_list(l1, m1, rank1, top1, shift, lane);
        if (!en2) ansu2 = top2;
        else ansu2 = solve_list(l2, m2, rank2, top2, shift, lane);
    }

    if (lane == 0) {
        g_t1[pos] = u2f(ansu1);
        g_t2[pos] = u2f(ansu2);
    }
}

// ---------------------------------------------------------------------------
// Kernel 3: masks + (avg_pool_ceil(5,3) o adaptive(6)) as separable 6x27 map A.
// ---------------------------------------------------------------------------
__global__ void __launch_bounds__(128) pool_kernel(const float* __restrict__ bias,
                                                   float* __restrict__ out)
{
    __shared__ float st1[NPOS9], st2[NPOS9];
    __shared__ float sA[6][28];

    const int b = blockIdx.y;
    const int c = blockIdx.x * 128 + threadIdx.x;

    for (int i = threadIdx.x; i < NPOS9; i += 128) {
        st1[i] = g_t1[b * NPOS9 + i];
        st2[i] = g_t2[b * NPOS9 + i];
    }
    if (threadIdx.x < 27) {
        int wcol = threadIdx.x;
        const int sidx[6] = {0, 1, 3, 4, 6, 7};
        #pragma unroll
        for (int i = 0; i < 6; i++) {
            float a = 0.0f;
            #pragma unroll
            for (int q = 0; q < 2; q++) {
                int p = sidx[i] + q;
                int st = 3 * p, en = (st + 5 < 27) ? st + 5 : 27;
                if (wcol >= st && wcol < en) a += 0.5f / (float)(en - st);
            }
            sA[i][wcol] = a;
        }
    }
    __syncthreads();

    const float bc = bias[c];
    const float* p = g_conv + (size_t)b * NPOS9 * NC + c;

    float acc1[36], acc2[36];
    #pragma unroll
    for (int k = 0; k < 36; k++) { acc1[k] = 0.0f; acc2[k] = 0.0f; }

    int idx = 0;
    for (int h = 0; h < 27; h++) {
        float r1[6], r2[6];
        #pragma unroll
        for (int j = 0; j < 6; j++) { r1[j] = 0.0f; r2[j] = 0.0f; }
        for (int wcol = 0; wcol < 27; wcol++, idx++) {
            float v = __ldg(p + (size_t)idx * NC);
            float m1 = (bc - v < st1[idx]) ? 1.0f : 0.0f;
            float m2 = (bc + v < st2[idx]) ? 1.0f : 0.0f;
            #pragma unroll
            for (int j = 0; j < 6; j++) {
                float a = sA[j][wcol];
                r1[j] += a * m1;
                r2[j] += a * m2;
            }
        }
        #pragma unroll
        for (int i = 0; i < 6; i++) {
            float ah = sA[i][h];
            #pragma unroll
            for (int j = 0; j < 6; j++) {
                acc1[i * 6 + j] += ah * r1[j];
                acc2[i * 6 + j] += ah * r2[j];
            }
        }
    }

    float* o1 = out + ((size_t)(b * NC + c)) * 36;
    float* o2 = o1 + (size_t)NB * NC * 36;
    #pragma unroll
    for (int k = 0; k < 36; k++) { o1[k] = acc1[k]; o2[k] = acc2[k]; }
}

// ---------------------------------------------------------------------------
extern "C" void kernel_launch(void* const* d_in, const int* in_sizes, int n_in,
                              void* d_out, int out_size)
{
    const float* x    = (const float*)d_in[0]; // [64,3,32,32]
    const float* w    = (const float*)d_in[1]; // [2048,3,6,6]
    const float* bias = (const float*)d_in[2]; // [2048]
    float* out = (float*)d_out;                // [2][64,2048,6,6]

    cudaFuncSetAttribute(conv_kernel, cudaFuncAttributeMaxDynamicSharedMemorySize, CONV_SMEM);
    cudaFuncSetAttribute(select_kernel, cudaFuncAttributeMaxDynamicSharedMemorySize, SEL_SMEM);

    conv_kernel<<<dim3(16, 64), 256, CONV_SMEM>>>(x, w);
    select_kernel<<<TOTPOS / 4, 128, SEL_SMEM>>>(bias);
    pool_kernel<<<dim3(16, 64), 128>>>(bias, out);
}